// round 3
// baseline (speedup 1.0000x reference)
#include <cuda_runtime.h>

// SSIM loss, fused separable 11x11 Gaussian depthwise conv, packed f32x2 math.
// Inputs: img1, img2 : [32,3,512,512] fp32. Output: scalar float = 1 - mean(ssim_map).
// Single kernel: per-tile SSIM partial sums + last-block deterministic finalize.

#define PLANE     512
#define TW        64
#define TH        32
#define VCOLS     74                 // TW + 10 (x halo)
#define CSTRIDE   34                 // floats per smem column (TH + 2 pad)
#define FSTRIDE   (VCOLS * CSTRIDE)  // 2516 floats per field
#define NTHREADS  320
#define NTILE_X   8
#define NTILE_Y   16
#define NPLANES   96
#define NPART     (NTILE_X * NTILE_Y * NPLANES)   // 12288

__device__ float g_partial[NPART];
__device__ unsigned int g_count;     // zero-initialized; reset by last block

typedef unsigned long long u64;

__device__ __forceinline__ u64 bcast2(float v) {
    u64 r; asm("mov.b64 %0, {%1, %1};" : "=l"(r) : "f"(v)); return r;
}
__device__ __forceinline__ u64 pack2(float lo, float hi) {
    u64 r; asm("mov.b64 %0, {%1, %2};" : "=l"(r) : "f"(lo), "f"(hi)); return r;
}
__device__ __forceinline__ void unpack2(u64 v, float& lo, float& hi) {
    asm("mov.b64 {%0, %1}, %2;" : "=f"(lo), "=f"(hi) : "l"(v));
}
__device__ __forceinline__ u64 fma2(u64 a, u64 b, u64 c) {
    u64 d; asm("fma.rn.f32x2 %0, %1, %2, %3;" : "=l"(d) : "l"(a), "l"(b), "l"(c)); return d;
}
__device__ __forceinline__ u64 mul2(u64 a, u64 b) {
    u64 d; asm("mul.rn.f32x2 %0, %1, %2;" : "=l"(d) : "l"(a), "l"(b)); return d;
}
__device__ __forceinline__ u64 add2(u64 a, u64 b) {
    u64 d; asm("add.rn.f32x2 %0, %1, %2;" : "=l"(d) : "l"(a), "l"(b)); return d;
}

__global__ void __launch_bounds__(NTHREADS, 2)
ssim_kernel(const float* __restrict__ img1, const float* __restrict__ img2,
            float* __restrict__ out)
{
    extern __shared__ float sm[];    // 5 * FSTRIDE floats = 50320 B

    const int tid = threadIdx.x;
    const int x0  = blockIdx.x * TW;
    const int y0  = blockIdx.y * TH;
    const float* __restrict__ p1 = img1 + (size_t)blockIdx.z * (PLANE * PLANE);
    const float* __restrict__ p2 = img2 + (size_t)blockIdx.z * (PLANE * PLANE);

    // Gaussian(11, sigma=1.5) weights + packed weight pairs W2[idx] = (w[idx], w[idx-1]).
    constexpr float KW[11] = {
        0.0010284f, 0.0075988f, 0.0360008f, 0.1093607f, 0.2130055f,
        0.2660117f,
        0.2130055f, 0.1093607f, 0.0360008f, 0.0075988f, 0.0010284f
    };
    u64 W2[12];
    W2[0] = pack2(KW[0], 0.f);
    #pragma unroll
    for (int i = 1; i <= 10; ++i) W2[i] = pack2(KW[i], KW[i - 1]);
    W2[11] = pack2(0.f, KW[10]);

    // ---------------- Vertical pass (global -> smem, packed pairs of rows) ----
    // 296 tasks: column c (0..73) x strip (0..3), strip = 8 output rows = 4 pairs.
    if (tid < VCOLS * 4) {
        const int c     = tid % VCOLS;
        const int strip = tid / VCOLS;
        const int gx    = x0 + c - 5;
        const bool xok  = ((unsigned)gx < (unsigned)PLANE);
        const int ybase = y0 + strip * 8 - 5;

        u64 A1[4], A2[4], E11[4], E22[4], E12[4];
        #pragma unroll
        for (int p = 0; p < 4; ++p) { A1[p]=0; A2[p]=0; E11[p]=0; E22[p]=0; E12[p]=0; }

        #pragma unroll
        for (int j = 0; j < 18; ++j) {
            const int gy = ybase + j;
            const bool ok = xok && ((unsigned)gy < (unsigned)PLANE);
            const int idx = gy * PLANE + gx;
            float a1 = ok ? __ldg(p1 + idx) : 0.f;
            float a2 = ok ? __ldg(p2 + idx) : 0.f;
            u64 a1p = bcast2(a1);
            u64 a2p = bcast2(a2);
            u64 q1p  = mul2(a1p, a1p);
            u64 q2p  = mul2(a2p, a2p);
            u64 q12p = mul2(a1p, a2p);
            #pragma unroll
            for (int p = 0; p < 4; ++p) {
                const int w = j - 2 * p;
                if (w >= 0 && w <= 11) {
                    A1[p]  = fma2(a1p,  W2[w], A1[p]);
                    A2[p]  = fma2(a2p,  W2[w], A2[p]);
                    E11[p] = fma2(q1p,  W2[w], E11[p]);
                    E22[p] = fma2(q2p,  W2[w], E22[p]);
                    E12[p] = fma2(q12p, W2[w], E12[p]);
                }
            }
        }
        // Column-major smem: one STS.64 stores the (row 2p, row 2p+1) pair.
        const int cb = c * CSTRIDE + strip * 8;
        #pragma unroll
        for (int p = 0; p < 4; ++p) {
            *(u64*)(sm + 0 * FSTRIDE + cb + 2 * p) = A1[p];
            *(u64*)(sm + 1 * FSTRIDE + cb + 2 * p) = A2[p];
            *(u64*)(sm + 2 * FSTRIDE + cb + 2 * p) = E11[p];
            *(u64*)(sm + 3 * FSTRIDE + cb + 2 * p) = E22[p];
            *(u64*)(sm + 4 * FSTRIDE + cb + 2 * p) = E12[p];
        }
    }
    __syncthreads();

    // ---------------- Horizontal pass (smem -> SSIM map -> local sum) --------
    // 256 tasks: row (0..31) x segment (0..7), segment = 8 output cols = 4 pairs.
    float lsum = 0.f;
    if (tid < TH * 8) {
        const int r   = tid & 31;        // warp = one segment, 32 rows -> conflict-free LDS
        const int seg = tid >> 5;
        const int c0  = seg * 8;

        u64 M1[4], M2[4], S11[4], S22[4], S12[4];
        #pragma unroll
        for (int p = 0; p < 4; ++p) { M1[p]=0; M2[p]=0; S11[p]=0; S22[p]=0; S12[p]=0; }

        #pragma unroll
        for (int j = 0; j < 18; ++j) {
            const int cb = (c0 + j) * CSTRIDE + r;
            u64 b0 = bcast2(sm[0 * FSTRIDE + cb]);
            u64 b1 = bcast2(sm[1 * FSTRIDE + cb]);
            u64 b2 = bcast2(sm[2 * FSTRIDE + cb]);
            u64 b3 = bcast2(sm[3 * FSTRIDE + cb]);
            u64 b4 = bcast2(sm[4 * FSTRIDE + cb]);
            #pragma unroll
            for (int p = 0; p < 4; ++p) {
                const int w = j - 2 * p;
                if (w >= 0 && w <= 11) {
                    M1[p]  = fma2(b0, W2[w], M1[p]);
                    M2[p]  = fma2(b1, W2[w], M2[p]);
                    S11[p] = fma2(b2, W2[w], S11[p]);
                    S22[p] = fma2(b3, W2[w], S22[p]);
                    S12[p] = fma2(b4, W2[w], S12[p]);
                }
            }
        }

        const u64 SGN = 0x8000000080000000ULL;
        const u64 twop = bcast2(2.f);
        const u64 c1p  = bcast2(1e-4f);    // (0.01)^2
        const u64 c2p  = bcast2(9e-4f);    // (0.03)^2
        #pragma unroll
        for (int p = 0; p < 4; ++p) {
            u64 mu1 = M1[p], mu2 = M2[p];
            u64 nmu1 = mu1 ^ SGN;
            u64 nmu2 = mu2 ^ SGN;
            u64 mu12 = mul2(mu1, mu2);
            u64 s11  = fma2(nmu1, mu1, S11[p]);   // e11 - mu1^2
            u64 s22  = fma2(nmu2, mu2, S22[p]);   // e22 - mu2^2
            u64 s12  = fma2(nmu1, mu2, S12[p]);   // e12 - mu1*mu2
            u64 nump = mul2(fma2(mu12, twop, c1p), fma2(s12, twop, c2p));
            u64 denp = mul2(fma2(mu1, mu1, fma2(mu2, mu2, c1p)),
                            add2(add2(s11, s22), c2p));
            float nl, nh, dl, dh;
            unpack2(nump, nl, nh);
            unpack2(denp, dl, dh);
            lsum += __fdividef(nl, dl) + __fdividef(nh, dh);
        }
    }

    // ---------------- Block reduction (fixed order, deterministic) -----------
    #pragma unroll
    for (int off = 16; off > 0; off >>= 1)
        lsum += __shfl_down_sync(0xffffffffu, lsum, off);

    __shared__ float wsum[NTHREADS / 32];
    const int wid = tid >> 5, lane = tid & 31;
    if (lane == 0) wsum[wid] = lsum;
    __syncthreads();

    const int bid = ((int)blockIdx.z * NTILE_Y + (int)blockIdx.y) * NTILE_X + (int)blockIdx.x;
    if (tid == 0) {
        float s = 0.f;
        #pragma unroll
        for (int w = 0; w < NTHREADS / 32; ++w) s += wsum[w];
        g_partial[bid] = s;
    }

    // ---------------- Last-block deterministic finalize ----------------------
    __shared__ bool isLast;
    if (tid == 0) {
        __threadfence();
        unsigned old = atomicAdd(&g_count, 1u);
        isLast = (old == (unsigned)(NPART - 1));
    }
    __syncthreads();
    if (isLast) {
        __threadfence();
        double s = 0.0;
        for (int i = tid; i < NPART; i += NTHREADS)
            s += (double)__ldcg(g_partial + i);      // fixed per-thread order
        __shared__ double ds[NTHREADS];
        ds[tid] = s;
        __syncthreads();
        if (tid < 160) ds[tid] += ds[tid + 160]; __syncthreads();
        if (tid <  80) ds[tid] += ds[tid +  80]; __syncthreads();
        if (tid <  40) ds[tid] += ds[tid +  40]; __syncthreads();
        if (tid <  20) ds[tid] += ds[tid +  20]; __syncthreads();
        if (tid <  10) ds[tid] += ds[tid +  10]; __syncthreads();
        if (tid == 0) {
            double tot = 0.0;
            #pragma unroll
            for (int w = 0; w < 10; ++w) tot += ds[w];
            const double N = 32.0 * 3.0 * 512.0 * 512.0;
            out[0] = (float)(1.0 - tot / N);
            g_count = 0;                              // reset for next graph replay
        }
    }
}

extern "C" void kernel_launch(void* const* d_in, const int* in_sizes, int n_in,
                              void* d_out, int out_size)
{
    const float* img1 = (const float*)d_in[0];
    const float* img2 = (const float*)d_in[1];
    float* out = (float*)d_out;

    const int smem = 5 * FSTRIDE * (int)sizeof(float);   // 50320 B
    cudaFuncSetAttribute(ssim_kernel, cudaFuncAttributeMaxDynamicSharedMemorySize, smem);

    dim3 grid(NTILE_X, NTILE_Y, NPLANES);
    ssim_kernel<<<grid, NTHREADS, smem>>>(img1, img2, out);
}

// round 4
// speedup vs baseline: 1.3461x; 1.3461x over previous
#include <cuda_runtime.h>

// SSIM loss, fused separable 11x11 Gaussian depthwise conv.
// Algebraic reduction: only 4 conv fields needed (mu1, mu2, E[x^2+y^2], E[x*y]),
// since SSIM uses sigma1_sq + sigma2_sq only as a sum.
// Single kernel: per-tile partials + last-block deterministic finalize.

#define PLANE      512
#define TW         64
#define TH         48
#define VCOLS      74          // TW + 10 (x halo)
#define VSTRIDE    75          // smem row stride
#define NTHREADS   224
#define NTILE_X    8           // 512/64
#define NTILE_Y    11          // ceil(512/48)
#define NPLANES    96          // 32*3
#define NPART      (NTILE_X*NTILE_Y*NPLANES)   // 8448
#define NFIELDS    4

__device__ float g_partial[NPART];
__device__ unsigned int g_count;    // zero-init; reset by last block each replay

// Gaussian(11, sigma=1.5), normalized. Compile-time literals -> FFMA-imm (rt=1).
__device__ __forceinline__ float gw(int k) {
    constexpr float KW[11] = {
        0.0010284f, 0.0075988f, 0.0360008f, 0.1093607f, 0.2130055f,
        0.2660117f,
        0.2130055f, 0.1093607f, 0.0360008f, 0.0075988f, 0.0010284f
    };
    return KW[k];
}

__global__ void __launch_bounds__(NTHREADS, 3)
ssim_kernel(const float* __restrict__ img1, const float* __restrict__ img2,
            float* __restrict__ out)
{
    extern __shared__ float sm[];   // 4 * TH * VSTRIDE floats = 57600 B
    float* smF[NFIELDS];
    #pragma unroll
    for (int f = 0; f < NFIELDS; ++f) smF[f] = sm + f * (TH * VSTRIDE);

    const int tid = threadIdx.x;
    const int x0  = blockIdx.x * TW;
    const int y0  = blockIdx.y * TH;
    const float* __restrict__ p1 = img1 + (size_t)blockIdx.z * (PLANE * PLANE);
    const float* __restrict__ p2 = img2 + (size_t)blockIdx.z * (PLANE * PLANE);

    // ---------------- Vertical pass (global -> smem), 4 fields ----------------
    // 222 tasks: column c (0..73) x strip (0..2), strip = 16 output rows.
    if (tid < VCOLS * 3) {
        const int c     = tid % VCOLS;
        const int strip = tid / VCOLS;
        const int gx    = x0 + c - 5;
        const bool xok  = ((unsigned)gx < (unsigned)PLANE);
        const int ybase = y0 + strip * 16 - 5;

        float m1[16], m2[16], es[16], ep[16];
        #pragma unroll
        for (int r = 0; r < 16; ++r) { m1[r]=0.f; m2[r]=0.f; es[r]=0.f; ep[r]=0.f; }

        #pragma unroll
        for (int j = 0; j < 26; ++j) {
            const int gy = ybase + j;
            const bool ok = xok && ((unsigned)gy < (unsigned)PLANE);
            const int idx = gy * PLANE + gx;
            float a1 = ok ? __ldg(p1 + idx) : 0.f;
            float a2 = ok ? __ldg(p2 + idx) : 0.f;
            float qs = fmaf(a1, a1, a2 * a2);   // x^2 + y^2
            float qp = a1 * a2;                 // x * y
            #pragma unroll
            for (int k = 0; k < 11; ++k) {
                const int o = j - k;
                if (o >= 0 && o < 16) {
                    m1[o] = fmaf(gw(k), a1, m1[o]);
                    m2[o] = fmaf(gw(k), a2, m2[o]);
                    es[o] = fmaf(gw(k), qs, es[o]);
                    ep[o] = fmaf(gw(k), qp, ep[o]);
                }
            }
        }
        #pragma unroll
        for (int r = 0; r < 16; ++r) {
            const int row = strip * 16 + r;
            smF[0][row * VSTRIDE + c] = m1[r];
            smF[1][row * VSTRIDE + c] = m2[r];
            smF[2][row * VSTRIDE + c] = es[r];
            smF[3][row * VSTRIDE + c] = ep[r];
        }
    }
    __syncthreads();

    // ---------------- Horizontal pass (smem -> SSIM map -> local sum) --------
    // 192 tasks: row (0..47) x segment (0..3), segment = 16 output cols.
    float lsum = 0.f;
    if (tid < TH * 4) {
        const int row = tid >> 2;
        const int seg = tid & 3;
        const int c0  = seg * 16;
        const float* r0 = smF[0] + row * VSTRIDE + c0;
        const float* r1 = smF[1] + row * VSTRIDE + c0;
        const float* r2 = smF[2] + row * VSTRIDE + c0;
        const float* r3 = smF[3] + row * VSTRIDE + c0;

        float m1[16], m2[16], es[16], ep[16];
        #pragma unroll
        for (int o = 0; o < 16; ++o) { m1[o]=0.f; m2[o]=0.f; es[o]=0.f; ep[o]=0.f; }

        #pragma unroll
        for (int j = 0; j < 26; ++j) {
            float b0 = r0[j];
            float b1 = r1[j];
            float b2 = r2[j];
            float b3 = r3[j];
            #pragma unroll
            for (int k = 0; k < 11; ++k) {
                const int o = j - k;
                if (o >= 0 && o < 16) {
                    m1[o] = fmaf(gw(k), b0, m1[o]);
                    m2[o] = fmaf(gw(k), b1, m2[o]);
                    es[o] = fmaf(gw(k), b2, es[o]);
                    ep[o] = fmaf(gw(k), b3, ep[o]);
                }
            }
        }

        const int gy = y0 + row;
        if (gy < PLANE) {
            const float C1 = 0.0001f;   // (0.01)^2
            const float C2 = 0.0009f;   // (0.03)^2
            #pragma unroll
            for (int o = 0; o < 16; ++o) {
                float mu1 = m1[o], mu2 = m2[o];
                float mu12   = mu1 * mu2;                      // mu1*mu2
                float musqs  = fmaf(mu1, mu1, mu2 * mu2);      // mu1^2 + mu2^2
                float s12    = ep[o] - mu12;                   // sigma12
                float ssum   = es[o] - musqs;                  // sigma1^2 + sigma2^2
                float num = fmaf(2.f, mu12, C1) * fmaf(2.f, s12, C2);
                float den = (musqs + C1) * (ssum + C2);
                lsum += __fdividef(num, den);
            }
        }
    }

    // ---------------- Block reduction (fixed order, deterministic) -----------
    #pragma unroll
    for (int off = 16; off > 0; off >>= 1)
        lsum += __shfl_down_sync(0xffffffffu, lsum, off);

    __shared__ float wsum[NTHREADS / 32];
    const int wid = tid >> 5, lane = tid & 31;
    if (lane == 0) wsum[wid] = lsum;
    __syncthreads();

    const int bid = ((int)blockIdx.z * NTILE_Y + (int)blockIdx.y) * NTILE_X + (int)blockIdx.x;
    if (tid == 0) {
        float s = 0.f;
        #pragma unroll
        for (int w = 0; w < NTHREADS / 32; ++w) s += wsum[w];
        g_partial[bid] = s;
    }

    // ---------------- Last-block deterministic finalize ----------------------
    __shared__ bool isLast;
    if (tid == 0) {
        __threadfence();
        unsigned old = atomicAdd(&g_count, 1u);
        isLast = (old == (unsigned)(NPART - 1));
    }
    __syncthreads();
    if (isLast) {
        __threadfence();
        double s = 0.0;
        for (int i = tid; i < NPART; i += NTHREADS)
            s += (double)__ldcg(g_partial + i);     // fixed per-thread order
        __shared__ double ds[NTHREADS];
        ds[tid] = s;
        __syncthreads();
        if (tid < 112) ds[tid] += ds[tid + 112]; __syncthreads();
        if (tid <  56) ds[tid] += ds[tid +  56]; __syncthreads();
        if (tid <  28) ds[tid] += ds[tid +  28]; __syncthreads();
        if (tid <  14) ds[tid] += ds[tid +  14]; __syncthreads();
        if (tid <   7) ds[tid] += ds[tid +   7]; __syncthreads();
        if (tid == 0) {
            double tot = 0.0;
            #pragma unroll
            for (int w = 0; w < 7; ++w) tot += ds[w];
            const double N = 32.0 * 3.0 * 512.0 * 512.0;
            out[0] = (float)(1.0 - tot / N);
            g_count = 0;                             // reset for next graph replay
        }
    }
}

extern "C" void kernel_launch(void* const* d_in, const int* in_sizes, int n_in,
                              void* d_out, int out_size)
{
    const float* img1 = (const float*)d_in[0];
    const float* img2 = (const float*)d_in[1];
    float* out = (float*)d_out;

    const int smem = NFIELDS * TH * VSTRIDE * (int)sizeof(float);   // 57600 B
    cudaFuncSetAttribute(ssim_kernel, cudaFuncAttributeMaxDynamicSharedMemorySize, smem);

    dim3 grid(NTILE_X, NTILE_Y, NPLANES);
    ssim_kernel<<<grid, NTHREADS, smem>>>(img1, img2, out);
}